// round 4
// baseline (speedup 1.0000x reference)
#include <cuda_runtime.h>
#include <cuda_fp16.h>
#include <cstdint>

// ---------------- static scratch ----------------
#define TBITS 21
#define TSIZE (1u << TBITS)
#define TMASK (TSIZE - 1u)
#define EMPTYK 0xFFFFFFFFu
#define MAXE 1050624
#define MAXN 40960
#define DUPCAP 262144

__device__ unsigned int  g_hkey[TSIZE];
__device__ unsigned char g_dupflag[TSIZE];
__device__ int           g_dupid[TSIZE];
__device__ int           g_soe[MAXE];
__device__ __align__(16) float g_agg[MAXN * 64];
__device__ __align__(16) float g_dupsum[(size_t)DUPCAP * 64];
__device__ int           g_ndup;

// ---------------- helpers ----------------
__device__ __forceinline__ unsigned int mixh(unsigned int x) {
    x ^= x >> 16; x *= 0x7feb352du;
    x ^= x >> 15; x *= 0x846ca68bu;
    x ^= x >> 16; return x;
}

__device__ __forceinline__ void red4(float* p, float4 v) {
    asm volatile("red.global.add.v4.f32 [%0], {%1,%2,%3,%4};"
                 :: "l"(p), "f"(v.x), "f"(v.y), "f"(v.z), "f"(v.w) : "memory");
}

// fp16 split: x -> hi(f16x2) + lo(f16x2 of residual); elem .x in low half
__device__ __forceinline__ void cvt_split(float2 x, uint32_t& hi, uint32_t& lo) {
    __half2 h = __float22half2_rn(x);
    float2 hb = __half22float2(h);
    __half2 l = __floats2half2_rn(x.x - hb.x, x.y - hb.y);
    hi = *(uint32_t*)&h;
    lo = *(uint32_t*)&l;
}

__device__ __forceinline__ void mma16816(float* c, const uint32_t* a,
                                         uint32_t b0, uint32_t b1) {
    asm("mma.sync.aligned.m16n8k16.row.col.f32.f16.f16.f32 "
        "{%0,%1,%2,%3}, {%4,%5,%6,%7}, {%8,%9}, {%0,%1,%2,%3};"
        : "+f"(c[0]), "+f"(c[1]), "+f"(c[2]), "+f"(c[3])
        : "r"(a[0]), "r"(a[1]), "r"(a[2]), "r"(a[3]), "r"(b0), "r"(b1));
}

// ---------------- kernel: hash insert + node aggregation ----------------
__global__ __launch_bounds__(256) void k_insert(const float* __restrict__ ef,
                                                const int* __restrict__ esrc,
                                                const int* __restrict__ edst,
                                                int nn, int E) {
    int i = blockIdx.x * 256 + threadIdx.x;
    if (i >= E) return;
    int s = esrc[i], d = edst[i];
    unsigned int key = (unsigned int)s * (unsigned int)nn + (unsigned int)d;
    unsigned int h = mixh(key) & TMASK;
    for (;;) {
        unsigned int prev = atomicCAS(&g_hkey[h], EMPTYK, key);
        if (prev == EMPTYK) break;
        if (prev == key) { g_dupflag[h] = 1; break; }
        h = (h + 1u) & TMASK;
    }
    g_soe[i] = (int)h;

    const float4* row = (const float4*)(ef + (size_t)i * 64);
    float* ar = g_agg + (size_t)d * 64;
#pragma unroll
    for (int c = 0; c < 16; c++) red4(ar + 4 * c, row[c]);
}

// ---------------- kernel: assign dup ids ----------------
__global__ void k_dupassign() {
    int t = blockIdx.x * 256 + threadIdx.x;
    if (t >= (int)TSIZE) return;
    if (g_dupflag[t]) {
        int d = atomicAdd(&g_ndup, 1);
        if (d < DUPCAP) {
            g_dupid[t] = d;
            float4* p = (float4*)(g_dupsum + (size_t)d * 64);
#pragma unroll
            for (int c = 0; c < 16; c++) p[c] = make_float4(0.f, 0.f, 0.f, 0.f);
        } else g_dupid[t] = -1;
    } else {
        g_dupid[t] = -1;
    }
}

// ---------------- kernel: accumulate duplicated groups ----------------
__global__ __launch_bounds__(256) void k_dupacc(const float* __restrict__ ef, int E) {
    int i = blockIdx.x * 256 + threadIdx.x;
    if (i >= E) return;
    int d = g_dupid[g_soe[i]];
    if (d < 0) return;
    const float4* row = (const float4*)(ef + (size_t)i * 64);
    float* p = g_dupsum + (size_t)d * 64;
#pragma unroll
    for (int c = 0; c < 16; c++) red4(p + 4 * c, row[c]);
}

// ---------------- fused: mirror-paired tiles, HMMA, single ef read ----------------
// Warp-tile: 16 first-half edges + their 16 mirrors (M=32) x N=64, K=128.
// Rev data for row j (non-dup) = ef pairs of partner row j^2 (in-register).
// 3-product fp16 split: xh*wh + xl*wh + xh*wl.
__global__ __launch_bounds__(256, 2) void k_fused_mma(const float* __restrict__ ef,
                                                      const int* __restrict__ esrc,
                                                      const float* __restrict__ W,
                                                      const float* __restrict__ bias,
                                                      float* __restrict__ out, int E) {
    __shared__ uint4 Bf[8][8][32];     // [kb][nb][lane] = (bh0,bh1,bl0,bl1)  32KB
    __shared__ float bias_sh[64];

    const int tid  = threadIdx.x;
    const int lane = tid & 31;
    const int wid  = tid >> 5;
    const int q    = lane & 3;
    const int g    = lane >> 2;

    // Build W fragments (hi & lo) packed per (kb,nb,lane).
    for (int idx = tid; idx < 2048; idx += 256) {
        int kb = idx >> 8, nb = (idx >> 5) & 7, L = idx & 31;
        int qq = L & 3, n = nb * 8 + (L >> 2);
        int k0 = kb * 16 + 2 * qq;
        uint32_t h0, l0, h1, l1;
        cvt_split(make_float2(W[k0 * 64 + n], W[(k0 + 1) * 64 + n]), h0, l0);
        cvt_split(make_float2(W[(k0 + 8) * 64 + n], W[(k0 + 9) * 64 + n]), h1, l1);
        Bf[kb][nb][L] = make_uint4(h0, h1, l0, l1);
    }
    if (tid < 64) bias_sh[tid] = bias[tid];
    __syncthreads();

    const int E2 = E >> 1;
    const int ntiles = (E2 + 15) >> 4;

    for (int t = blockIdx.x * 8 + wid; t < ntiles; t += gridDim.x * 8) {
        const int base = t * 16;
        int e[4]; bool val[2];
        uint32_t oef[4], oagg[4], odup[4];
#pragma unroll
        for (int j2 = 0; j2 < 2; j2++) {
            int f = base + 8 * j2 + g;
            bool v = f < E2;
            int fc = v ? f : 0;
            e[j2] = fc; e[2 + j2] = fc + E2;
            val[j2] = v;
        }
#pragma unroll
        for (int j = 0; j < 4; j++) {
            oef[j]  = (uint32_t)e[j] * 256u;
            oagg[j] = (uint32_t)__ldg(&esrc[e[j]]) * 256u;
            int dp = g_dupid[g_soe[e[j ^ 2]]];
            odup[j] = (dp >= 0) ? (uint32_t)dp * 256u : 0xFFFFFFFFu;
        }

        float acc[2][8][4];
#pragma unroll
        for (int mb = 0; mb < 2; mb++)
#pragma unroll
            for (int nb = 0; nb < 8; nb++)
#pragma unroll
                for (int c = 0; c < 4; c++) acc[mb][nb][c] = 0.f;

#pragma unroll
        for (int kb = 0; kb < 4; kb++) {
            // raw ef pairs for all 4 rows (also serve as partner rev data)
            float2 xf[4][2];
#pragma unroll
            for (int j = 0; j < 4; j++) {
                const float2* p = (const float2*)((const char*)ef + oef[j]);
                xf[j][0] = p[kb * 8 + q];
                xf[j][1] = p[kb * 8 + q + 4];
            }
            // ---- phase A: W block kb (h = ef) ----
#pragma unroll
            for (int mb = 0; mb < 2; mb++) {
                uint32_t ah[4], al[4];
                cvt_split(xf[2 * mb + 0][0], ah[0], al[0]);
                cvt_split(xf[2 * mb + 1][0], ah[1], al[1]);
                cvt_split(xf[2 * mb + 0][1], ah[2], al[2]);
                cvt_split(xf[2 * mb + 1][1], ah[3], al[3]);
#pragma unroll
                for (int nb = 0; nb < 8; nb++) {
                    uint4 b = Bf[kb][nb][lane];
                    mma16816(acc[mb][nb], ah, b.x, b.y);
                    mma16816(acc[mb][nb], al, b.x, b.y);
                    mma16816(acc[mb][nb], ah, b.z, b.w);
                }
            }
            // ---- phase B: W block kb+4 (h = agg[src] - rev) ----
#pragma unroll
            for (int mb = 0; mb < 2; mb++) {
                uint32_t ah[4], al[4];
#pragma unroll
                for (int j2 = 0; j2 < 2; j2++) {
                    int j = 2 * mb + j2;
                    const float2* ap = (const float2*)((const char*)g_agg + oagg[j]);
                    float2 a0 = ap[kb * 8 + q], a1 = ap[kb * 8 + q + 4];
                    float2 r0, r1;
                    if (odup[j] != 0xFFFFFFFFu) {
                        const float2* rp = (const float2*)((const char*)g_dupsum + odup[j]);
                        r0 = rp[kb * 8 + q]; r1 = rp[kb * 8 + q + 4];
                    } else {
                        r0 = xf[j ^ 2][0]; r1 = xf[j ^ 2][1];
                    }
                    cvt_split(make_float2(a0.x - r0.x, a0.y - r0.y), ah[j2], al[j2]);
                    cvt_split(make_float2(a1.x - r1.x, a1.y - r1.y), ah[2 + j2], al[2 + j2]);
                }
#pragma unroll
                for (int nb = 0; nb < 8; nb++) {
                    uint4 b = Bf[kb + 4][nb][lane];
                    mma16816(acc[mb][nb], ah, b.x, b.y);
                    mma16816(acc[mb][nb], al, b.x, b.y);
                    mma16816(acc[mb][nb], ah, b.z, b.w);
                }
            }
        }

        // ---- epilogue: bias + relu + store (rows: c0/c1 -> e[2mb], c2/c3 -> e[2mb+1]) ----
#pragma unroll
        for (int mb = 0; mb < 2; mb++) {
            if (!val[0] && !val[1]) break;
#pragma unroll
            for (int nb = 0; nb < 8; nb++) {
                int col = nb * 8 + 2 * q;
                float2 bv = *(const float2*)(bias_sh + col);
                if (val[0]) {
                    float2 o = make_float2(fmaxf(acc[mb][nb][0] + bv.x, 0.f),
                                           fmaxf(acc[mb][nb][1] + bv.y, 0.f));
                    *(float2*)(out + (size_t)e[2 * mb] * 64 + col) = o;
                }
                if (val[1]) {
                    float2 o = make_float2(fmaxf(acc[mb][nb][2] + bv.x, 0.f),
                                           fmaxf(acc[mb][nb][3] + bv.y, 0.f));
                    *(float2*)(out + (size_t)e[2 * mb + 1] * 64 + col) = o;
                }
            }
        }
    }
}

// ---------------- launch ----------------
extern "C" void kernel_launch(void* const* d_in, const int* in_sizes, int n_in,
                              void* d_out, int out_size) {
    const float* ef   = (const float*)d_in[0];
    const int*   esrc = (const int*)d_in[1];
    const int*   edst = (const int*)d_in[2];
    const float* W    = (const float*)d_in[5];
    const float* bias = (const float*)d_in[6];
    float* out = (float*)d_out;

    int E  = in_sizes[1];
    int nn = in_sizes[3];

    void *p_hkey, *p_flag, *p_agg, *p_ndup;
    cudaGetSymbolAddress(&p_hkey, g_hkey);
    cudaGetSymbolAddress(&p_flag, g_dupflag);
    cudaGetSymbolAddress(&p_agg,  g_agg);
    cudaGetSymbolAddress(&p_ndup, g_ndup);

    cudaMemsetAsync(p_hkey, 0xFF, (size_t)TSIZE * 4);
    cudaMemsetAsync(p_flag, 0x00, (size_t)TSIZE);
    cudaMemsetAsync(p_agg,  0x00, (size_t)nn * 64 * 4);
    cudaMemsetAsync(p_ndup, 0x00, 4);

    k_insert<<<(E + 255) / 256, 256>>>(ef, esrc, edst, nn, E);
    k_dupassign<<<((int)TSIZE + 255) / 256, 256>>>();
    k_dupacc<<<(E + 255) / 256, 256>>>(ef, E);

    k_fused_mma<<<296, 256>>>(ef, esrc, W, bias, out, E);
}